// round 6
// baseline (speedup 1.0000x reference)
#include <cuda_runtime.h>
#include <cuda_fp16.h>
#include <cstdint>

#define N_NODES  100000
#define N_EDGES  1600000
#define IN_CH    128
#define HID      128
#define OUT_CH   64
#define N_GRAPHS 512

static const int NB_SCAN = (N_NODES + 1023) / 1024;   // 98

// ---------------- scratch (device globals) ----------------------------------
__device__ int    g_deg[N_NODES];
__device__ int    g_incl[N_NODES];
__device__ int    g_bsum[128];
__device__ int    g_rowptr[N_NODES + 1];
__device__ int    g_cursor[N_NODES];
__device__ int    g_srcidx[N_EDGES];
__device__ float  g_dinv[N_NODES];
__device__ __half g_hs[(size_t)N_NODES * HID];     // fp16 features (gather source)
__device__ float4 g_h2[N_NODES * (HID / 4)];       // conv output (fp32)

// ---------------- degree / CSR build ---------------------------------------
__global__ void k_zero_deg() {
    int i = blockIdx.x * blockDim.x + threadIdx.x;
    if (i < N_NODES) g_deg[i] = 0;
}

__global__ void k_count(const int* __restrict__ ei) {
    int e = blockIdx.x * blockDim.x + threadIdx.x;
    if (e < N_EDGES) atomicAdd(&g_deg[ei[N_EDGES + e]], 1);
}

__global__ void k_scan1() {
    __shared__ int s[1024];
    int t = threadIdx.x;
    int i = blockIdx.x * 1024 + t;
    int v = (i < N_NODES) ? g_deg[i] : 0;
    s[t] = v;
    __syncthreads();
    for (int off = 1; off < 1024; off <<= 1) {
        int a = (t >= off) ? s[t - off] : 0;
        __syncthreads();
        s[t] += a;
        __syncthreads();
    }
    if (i < N_NODES) g_incl[i] = s[t];
    if (t == 1023) g_bsum[blockIdx.x] = s[1023];
}

// scan3 computes its own block-offset from g_bsum (no separate scan2 kernel)
__global__ void k_scan3(int nb) {
    __shared__ int tmp[128];
    __shared__ int soff;
    int t = threadIdx.x;
    if (t < 128) tmp[t] = (t < (int)blockIdx.x && t < nb) ? g_bsum[t] : 0;
    __syncthreads();
    if (t == 0) {
        int s = 0;
#pragma unroll
        for (int j = 0; j < 128; j++) s += tmp[j];
        soff = s;
    }
    __syncthreads();
    int i = blockIdx.x * 1024 + t;
    if (i < N_NODES) {
        int d = g_deg[i];
        int v = g_incl[i] - d + soff;      // exclusive prefix
        g_rowptr[i] = v;
        g_cursor[i] = v;
        g_dinv[i]   = rsqrtf((float)(d + 1));
    }
    if (i == 0) g_rowptr[N_NODES] = N_EDGES;
}

__global__ void k_scatter(const int* __restrict__ ei) {
    int e = blockIdx.x * blockDim.x + threadIdx.x;
    if (e < N_EDGES) {
        int s = ei[e];
        int d = ei[N_EDGES + e];
        g_srcidx[atomicAdd(&g_cursor[d], 1)] = s;
    }
}

// ---------------- precision-split tensor-core GEMM (128x128 W, K=128) -------
// out[row] = fp16( scale[row] * (X[row] @ W) ) via 3 MMAs per tile:
//   A_hi*W_hi + A_hi*W_lo + A_lo*W_hi   (fp16 split, fp32 accumulate)
__global__ void __launch_bounds__(256) k_gemm_mma(
        const float* __restrict__ X, const float* __restrict__ W,
        const float* __restrict__ scale, __half* __restrict__ out, int M) {
    constexpr int NT = 16;                        // 128 cols / 8
    constexpr int AS = 136;                       // padded stride (halves)
    extern __shared__ __half sm[];
    __half* Ahi = sm;                             // [128][AS]
    __half* Alo = Ahi + 128 * AS;
    __half* Bhi = Alo + 128 * AS;                 // [128][AS] (n,k)
    __half* Blo = Bhi + 128 * AS;
    int t = threadIdx.x;
    int rowBase = blockIdx.x * 128;

    // stage A split (fp32 -> hi + lo)
    for (int idx = t; idx < 128 * 32; idx += 256) {
        int r = idx >> 5, c4 = idx & 31;
        float4 v = make_float4(0.f, 0.f, 0.f, 0.f);
        int gr = rowBase + r;
        if (gr < M) v = ((const float4*)X)[(size_t)gr * 32 + c4];
        __half2 h01 = __floats2half2_rn(v.x, v.y);
        __half2 h23 = __floats2half2_rn(v.z, v.w);
        float2 f01 = __half22float2(h01);
        float2 f23 = __half22float2(h23);
        __half2 l01 = __floats2half2_rn(v.x - f01.x, v.y - f01.y);
        __half2 l23 = __floats2half2_rn(v.z - f23.x, v.w - f23.y);
        *(__half2*)&Ahi[r * AS + c4 * 4]     = h01;
        *(__half2*)&Ahi[r * AS + c4 * 4 + 2] = h23;
        *(__half2*)&Alo[r * AS + c4 * 4]     = l01;
        *(__half2*)&Alo[r * AS + c4 * 4 + 2] = l23;
    }
    // stage W split, transposed: B[n][k] = W[k][n]
    for (int idx = t; idx < 128 * 128; idx += 256) {
        int k = idx >> 7, n = idx & 127;
        float w = W[idx];
        __half h = __float2half_rn(w);
        Bhi[n * AS + k] = h;
        Blo[n * AS + k] = __float2half_rn(w - __half2float(h));
    }
    __syncthreads();

    int w = t >> 5, lane = t & 31;
    int g = lane >> 2, s = lane & 3;
    int strip = w * 16;

    float acc[NT][4];
#pragma unroll
    for (int nt = 0; nt < NT; nt++)
#pragma unroll
        for (int q = 0; q < 4; q++) acc[nt][q] = 0.f;

    const int aoff0 = (strip + g) * AS + s * 2;
    const int aoff1 = aoff0 + 8 * AS;
#pragma unroll
    for (int ks = 0; ks < 8; ks++) {
        int kb = ks * 16;
        unsigned ah0 = *(const unsigned*)(Ahi + aoff0 + kb);
        unsigned ah1 = *(const unsigned*)(Ahi + aoff1 + kb);
        unsigned ah2 = *(const unsigned*)(Ahi + aoff0 + kb + 8);
        unsigned ah3 = *(const unsigned*)(Ahi + aoff1 + kb + 8);
        unsigned al0 = *(const unsigned*)(Alo + aoff0 + kb);
        unsigned al1 = *(const unsigned*)(Alo + aoff1 + kb);
        unsigned al2 = *(const unsigned*)(Alo + aoff0 + kb + 8);
        unsigned al3 = *(const unsigned*)(Alo + aoff1 + kb + 8);
#pragma unroll
        for (int nt = 0; nt < NT; nt++) {
            int boff = (nt * 8 + g) * AS + kb + s * 2;
            unsigned bh0 = *(const unsigned*)(Bhi + boff);
            unsigned bh1 = *(const unsigned*)(Bhi + boff + 8);
            unsigned bl0 = *(const unsigned*)(Blo + boff);
            unsigned bl1 = *(const unsigned*)(Blo + boff + 8);
            asm volatile(
                "mma.sync.aligned.m16n8k16.row.col.f32.f16.f16.f32 "
                "{%0,%1,%2,%3}, {%4,%5,%6,%7}, {%8,%9}, {%0,%1,%2,%3};"
                : "+f"(acc[nt][0]), "+f"(acc[nt][1]), "+f"(acc[nt][2]), "+f"(acc[nt][3])
                : "r"(ah0), "r"(ah1), "r"(ah2), "r"(ah3), "r"(bh0), "r"(bh1));
            asm volatile(
                "mma.sync.aligned.m16n8k16.row.col.f32.f16.f16.f32 "
                "{%0,%1,%2,%3}, {%4,%5,%6,%7}, {%8,%9}, {%0,%1,%2,%3};"
                : "+f"(acc[nt][0]), "+f"(acc[nt][1]), "+f"(acc[nt][2]), "+f"(acc[nt][3])
                : "r"(ah0), "r"(ah1), "r"(ah2), "r"(ah3), "r"(bl0), "r"(bl1));
            asm volatile(
                "mma.sync.aligned.m16n8k16.row.col.f32.f16.f16.f32 "
                "{%0,%1,%2,%3}, {%4,%5,%6,%7}, {%8,%9}, {%0,%1,%2,%3};"
                : "+f"(acc[nt][0]), "+f"(acc[nt][1]), "+f"(acc[nt][2]), "+f"(acc[nt][3])
                : "r"(al0), "r"(al1), "r"(al2), "r"(al3), "r"(bh0), "r"(bh1));
        }
    }

    int gr0 = rowBase + strip + g;
    int gr1 = gr0 + 8;
    float dv0 = (gr0 < M) ? scale[gr0] : 0.f;
    float dv1 = (gr1 < M) ? scale[gr1] : 0.f;
#pragma unroll
    for (int nt = 0; nt < NT; nt++) {
        int col = nt * 8 + s * 2;
        if (gr0 < M)
            *(__half2*)&out[(size_t)gr0 * HID + col] =
                __floats2half2_rn(acc[nt][0] * dv0, acc[nt][1] * dv0);
        if (gr1 < M)
            *(__half2*)&out[(size_t)gr1 * HID + col] =
                __floats2half2_rn(acc[nt][2] * dv1, acc[nt][3] * dv1);
    }
}

// ---------------- aggregation: warp per node, 2 half-warps, LDG.128 ---------
__device__ __forceinline__ void acc8(float* a, uint4 u) {
    const __half2* h = (const __half2*)&u;
#pragma unroll
    for (int j = 0; j < 4; j++) {
        float2 f = __half22float2(h[j]);
        a[2 * j]     += f.x;
        a[2 * j + 1] += f.y;
    }
}

__global__ void __launch_bounds__(256) k_agg(
        const uint4* __restrict__ hs, const float* __restrict__ bias,
        float4* __restrict__ out) {
    int warp = (blockIdx.x * blockDim.x + threadIdx.x) >> 5;
    int lane = threadIdx.x & 31;
    if (warp >= N_NODES) return;
    int hw = lane >> 4, c = lane & 15;

    float a[8] = {0.f, 0.f, 0.f, 0.f, 0.f, 0.f, 0.f, 0.f};
    if (hw == 0) acc8(a, hs[(size_t)warp * 16 + c]);   // self loop

    int s0 = g_rowptr[warp];
    int s1 = g_rowptr[warp + 1];
    int i = s0 + hw;
    for (; i + 6 < s1; i += 8) {
        int e0 = g_srcidx[i];
        int e1 = g_srcidx[i + 2];
        int e2 = g_srcidx[i + 4];
        int e3 = g_srcidx[i + 6];
        uint4 v0 = hs[(size_t)e0 * 16 + c];
        uint4 v1 = hs[(size_t)e1 * 16 + c];
        uint4 v2 = hs[(size_t)e2 * 16 + c];
        uint4 v3 = hs[(size_t)e3 * 16 + c];
        acc8(a, v0); acc8(a, v1); acc8(a, v2); acc8(a, v3);
    }
    for (; i < s1; i += 2) acc8(a, hs[(size_t)g_srcidx[i] * 16 + c]);

#pragma unroll
    for (int q = 0; q < 8; q++) a[q] += __shfl_down_sync(0xffffffffu, a[q], 16);

    if (hw == 0) {
        float dv = g_dinv[warp];
        float4 b0 = ((const float4*)bias)[2 * c];
        float4 b1 = ((const float4*)bias)[2 * c + 1];
        float4 o0, o1;
        o0.x = fmaxf(fmaf(dv, a[0], b0.x), 0.f);
        o0.y = fmaxf(fmaf(dv, a[1], b0.y), 0.f);
        o0.z = fmaxf(fmaf(dv, a[2], b0.z), 0.f);
        o0.w = fmaxf(fmaf(dv, a[3], b0.w), 0.f);
        o1.x = fmaxf(fmaf(dv, a[4], b1.x), 0.f);
        o1.y = fmaxf(fmaf(dv, a[5], b1.y), 0.f);
        o1.z = fmaxf(fmaf(dv, a[6], b1.z), 0.f);
        o1.w = fmaxf(fmaf(dv, a[7], b1.w), 0.f);
        out[(size_t)warp * 32 + 2 * c]     = o0;
        out[(size_t)warp * 32 + 2 * c + 1] = o1;
    }
}

// ---------------- fused pool + MLP head (fp32, exact) -----------------------
// block g: pool graph g's rows, then relu(p@W3+b3) @ W4 + b4 -> out[g]
__global__ void __launch_bounds__(128) k_head(
        const float* __restrict__ h, const int* __restrict__ batch,
        const float* __restrict__ W3, const float* __restrict__ b3,
        const float* __restrict__ W4, const float* __restrict__ b4,
        float* __restrict__ out) {
    __shared__ float sp[128];
    __shared__ float sm2[128];
    int g = blockIdx.x;
    int c = threadIdx.x;

    int lo = 0, hi = N_NODES;
    while (lo < hi) { int mid = (lo + hi) >> 1; if (batch[mid] < g) lo = mid + 1; else hi = mid; }
    int start = lo;
    lo = start; hi = N_NODES;
    while (lo < hi) { int mid = (lo + hi) >> 1; if (batch[mid] < g + 1) lo = mid + 1; else hi = mid; }
    int end = lo;

    float acc = 0.f;
    for (int r = start; r < end; r++) acc += h[(size_t)r * HID + c];
    int cnt = end - start;
    sp[c] = acc / (float)(cnt > 0 ? cnt : 1);
    __syncthreads();

    float m = 0.f;
#pragma unroll 8
    for (int k = 0; k < HID; k++) m = fmaf(sp[k], W3[k * HID + c], m);
    sm2[c] = fmaxf(m + b3[c], 0.f);
    __syncthreads();

    if (c < OUT_CH) {
        float o = 0.f;
#pragma unroll 8
        for (int k = 0; k < HID; k++) o = fmaf(sm2[k], W4[k * OUT_CH + c], o);
        out[g * OUT_CH + c] = o + b4[c];
    }
}

// ---------------- launch ------------------------------------------------------
extern "C" void kernel_launch(void* const* d_in, const int* in_sizes, int n_in,
                              void* d_out, int out_size) {
    const float* x   = (const float*)d_in[0];
    const int*   ei  = (const int*)d_in[1];
    const int*   bat = (const int*)d_in[2];
    const float* W1  = (const float*)d_in[3];
    const float* b1  = (const float*)d_in[4];
    const float* W2  = (const float*)d_in[5];
    const float* b2  = (const float*)d_in[6];
    const float* W3  = (const float*)d_in[7];
    const float* b3  = (const float*)d_in[8];
    const float* W4  = (const float*)d_in[9];
    const float* b4  = (const float*)d_in[10];
    float* out = (float*)d_out;

    __half* hs; float4* h2; float* dinv;
    cudaGetSymbolAddress((void**)&hs,   g_hs);
    cudaGetSymbolAddress((void**)&h2,   g_h2);
    cudaGetSymbolAddress((void**)&dinv, g_dinv);

    const int SMG = 4 * 128 * 136 * 2;   // 139264 B (A hi/lo + B hi/lo)
    cudaFuncSetAttribute(k_gemm_mma, cudaFuncAttributeMaxDynamicSharedMemorySize, SMG);

    const int TB = 256;
    int nbN = (N_NODES + TB - 1) / TB;
    int nbE = (N_EDGES + TB - 1) / TB;
    int nbAgg = (N_NODES * 32 + TB - 1) / TB;
    int nbGemmN = (N_NODES + 127) / 128;    // 782

    // CSR build
    k_zero_deg<<<nbN, TB>>>();
    k_count<<<nbE, TB>>>(ei);
    k_scan1<<<NB_SCAN, 1024>>>();
    k_scan3<<<NB_SCAN, 1024>>>(NB_SCAN);
    k_scatter<<<nbE, TB>>>(ei);

    // conv1: hs = fp16(dinv * (x @ W1)); h2 = relu(dinv * gather(hs) + b1)
    k_gemm_mma<<<nbGemmN, 256, SMG>>>(x, W1, dinv, hs, N_NODES);
    k_agg<<<nbAgg, TB>>>((const uint4*)hs, b1, h2);

    // conv2
    k_gemm_mma<<<nbGemmN, 256, SMG>>>((const float*)h2, W2, dinv, hs, N_NODES);
    k_agg<<<nbAgg, TB>>>((const uint4*)hs, b2, h2);

    // fused pool + MLP head
    k_head<<<N_GRAPHS, 128>>>((const float*)h2, bat, W3, b3, W4, b4, out);
}

// round 7
// speedup vs baseline: 1.4920x; 1.4920x over previous
#include <cuda_runtime.h>
#include <cuda_fp16.h>
#include <cstdint>

#define N_NODES  100000
#define N_EDGES  1600000
#define IN_CH    128
#define HID      128
#define OUT_CH   64
#define N_GRAPHS 512

static const int NB_SCAN = (N_NODES + 1023) / 1024;   // 98

// ---------------- scratch (device globals) ----------------------------------
__device__ int    g_deg[N_NODES];
__device__ int    g_incl[N_NODES];
__device__ int    g_bsum[128];
__device__ int    g_rowptr[N_NODES + 1];
__device__ int    g_cursor[N_NODES];
__device__ int    g_srcidx[N_EDGES];
__device__ float  g_dinv[N_NODES];
__device__ __half g_hs[(size_t)N_NODES * HID];     // fp16 GEMM output (gather src)
__device__ __half g_h2[(size_t)N_NODES * HID];     // fp16 conv output

// ---------------- CSR build --------------------------------------------------
__global__ void k_count(const int* __restrict__ ei) {
    int e = blockIdx.x * blockDim.x + threadIdx.x;
    if (e < N_EDGES) atomicAdd(&g_deg[ei[N_EDGES + e]], 1);
}

__global__ void k_scan1() {
    __shared__ int s[1024];
    int t = threadIdx.x;
    int i = blockIdx.x * 1024 + t;
    int v = (i < N_NODES) ? g_deg[i] : 0;
    s[t] = v;
    __syncthreads();
    for (int off = 1; off < 1024; off <<= 1) {
        int a = (t >= off) ? s[t - off] : 0;
        __syncthreads();
        s[t] += a;
        __syncthreads();
    }
    if (i < N_NODES) g_incl[i] = s[t];
    if (t == 1023) g_bsum[blockIdx.x] = s[1023];
}

// scan3 computes its own block offset from g_bsum (no separate scan2 kernel)
__global__ void k_scan3(int nb) {
    __shared__ int tmp[128];
    __shared__ int soff;
    int t = threadIdx.x;
    if (t < 128) tmp[t] = (t < (int)blockIdx.x && t < nb) ? g_bsum[t] : 0;
    __syncthreads();
    if (t == 0) {
        int s = 0;
#pragma unroll
        for (int j = 0; j < 128; j++) s += tmp[j];
        soff = s;
    }
    __syncthreads();
    int i = blockIdx.x * 1024 + t;
    if (i < N_NODES) {
        int d = g_deg[i];
        int v = g_incl[i] - d + soff;      // exclusive prefix
        g_rowptr[i] = v;
        g_cursor[i] = v;
        g_dinv[i]   = rsqrtf((float)(d + 1));
    }
    if (i == 0) g_rowptr[N_NODES] = N_EDGES;
}

__global__ void k_scatter(const int* __restrict__ ei) {
    int e = blockIdx.x * blockDim.x + threadIdx.x;
    if (e < N_EDGES) {
        int s = ei[e];
        int d = ei[N_EDGES + e];
        g_srcidx[atomicAdd(&g_cursor[d], 1)] = s;
    }
}

// ---------------- tensor-core GEMM (128x128 W, K=128) -----------------------
// out[row] = fp16( scale[row] * (X[row] @ W) ), mma m16n8k16 fp16->fp32.
// HALF_IN: X rows already fp16 (straight 16B copies into smem).
template <bool HALF_IN>
__global__ void __launch_bounds__(256) k_gemm_mma(
        const void* __restrict__ Xv, const float* __restrict__ W,
        const float* __restrict__ scale, __half* __restrict__ out, int M) {
    constexpr int NT = 16;                        // 128 cols / 8
    constexpr int AS = 136;                       // padded stride (halves)
    extern __shared__ __half sm[];
    __half* Asm = sm;                             // [128][AS]
    __half* Bt  = sm + 128 * AS;                  // [128][AS] (n,k)
    int t = threadIdx.x;
    int rowBase = blockIdx.x * 128;

    if (HALF_IN) {
        const uint4* X = (const uint4*)Xv;        // 8 halves per chunk, 16/row
        for (int idx = t; idx < 128 * 16; idx += 256) {
            int r = idx >> 4, c8 = idx & 15;
            uint4 v = make_uint4(0u, 0u, 0u, 0u);
            int gr = rowBase + r;
            if (gr < M) v = X[(size_t)gr * 16 + c8];
            *(uint4*)&Asm[r * AS + c8 * 8] = v;
        }
    } else {
        const float4* X = (const float4*)Xv;
        for (int idx = t; idx < 128 * 32; idx += 256) {
            int r = idx >> 5, c4 = idx & 31;
            float4 v = make_float4(0.f, 0.f, 0.f, 0.f);
            int gr = rowBase + r;
            if (gr < M) v = X[(size_t)gr * 32 + c4];
            *(__half2*)&Asm[r * AS + c4 * 4]     = __floats2half2_rn(v.x, v.y);
            *(__half2*)&Asm[r * AS + c4 * 4 + 2] = __floats2half2_rn(v.z, v.w);
        }
    }
    // stage W transposed: Bt[n][k] = W[k][n]
    for (int idx = t; idx < 128 * 128; idx += 256) {
        int k = idx >> 7, n = idx & 127;
        Bt[n * AS + k] = __float2half_rn(W[idx]);
    }
    __syncthreads();

    int w = t >> 5, lane = t & 31;
    int g = lane >> 2, s = lane & 3;
    int strip = w * 16;

    float acc[NT][4];
#pragma unroll
    for (int nt = 0; nt < NT; nt++)
#pragma unroll
        for (int q = 0; q < 4; q++) acc[nt][q] = 0.f;

    const __half* Arow0 = &Asm[(strip + g) * AS + s * 2];
    const __half* Arow1 = Arow0 + 8 * AS;
#pragma unroll
    for (int ks = 0; ks < 8; ks++) {
        int kb = ks * 16;
        unsigned a0 = *(const unsigned*)(Arow0 + kb);
        unsigned a1 = *(const unsigned*)(Arow1 + kb);
        unsigned a2 = *(const unsigned*)(Arow0 + kb + 8);
        unsigned a3 = *(const unsigned*)(Arow1 + kb + 8);
#pragma unroll
        for (int nt = 0; nt < NT; nt++) {
            const __half* Bp = &Bt[(nt * 8 + g) * AS + kb + s * 2];
            unsigned b0 = *(const unsigned*)(Bp);
            unsigned b1 = *(const unsigned*)(Bp + 8);
            asm volatile(
                "mma.sync.aligned.m16n8k16.row.col.f32.f16.f16.f32 "
                "{%0,%1,%2,%3}, {%4,%5,%6,%7}, {%8,%9}, {%0,%1,%2,%3};"
                : "+f"(acc[nt][0]), "+f"(acc[nt][1]), "+f"(acc[nt][2]), "+f"(acc[nt][3])
                : "r"(a0), "r"(a1), "r"(a2), "r"(a3), "r"(b0), "r"(b1));
        }
    }

    int gr0 = rowBase + strip + g;
    int gr1 = gr0 + 8;
    float dv0 = (gr0 < M) ? scale[gr0] : 0.f;
    float dv1 = (gr1 < M) ? scale[gr1] : 0.f;
#pragma unroll
    for (int nt = 0; nt < NT; nt++) {
        int col = nt * 8 + s * 2;
        if (gr0 < M)
            *(__half2*)&out[(size_t)gr0 * HID + col] =
                __floats2half2_rn(acc[nt][0] * dv0, acc[nt][1] * dv0);
        if (gr1 < M)
            *(__half2*)&out[(size_t)gr1 * HID + col] =
                __floats2half2_rn(acc[nt][2] * dv1, acc[nt][3] * dv1);
    }
}

// ---------------- aggregation: warp per node, 2 half-warps, LDG.128 ---------
__device__ __forceinline__ void acc8(float* a, uint4 u) {
    const __half2* h = (const __half2*)&u;
#pragma unroll
    for (int j = 0; j < 4; j++) {
        float2 f = __half22float2(h[j]);
        a[2 * j]     += f.x;
        a[2 * j + 1] += f.y;
    }
}

__global__ void __launch_bounds__(256) k_agg(
        const uint4* __restrict__ hs, const float* __restrict__ bias,
        uint4* __restrict__ out) {
    int warp = (blockIdx.x * blockDim.x + threadIdx.x) >> 5;
    int lane = threadIdx.x & 31;
    if (warp >= N_NODES) return;
    int hw = lane >> 4, c = lane & 15;

    float a[8] = {0.f, 0.f, 0.f, 0.f, 0.f, 0.f, 0.f, 0.f};
    if (hw == 0) acc8(a, hs[(size_t)warp * 16 + c]);   // self loop

    int s0 = g_rowptr[warp];
    int s1 = g_rowptr[warp + 1];
    int i = s0 + hw;
    for (; i + 6 < s1; i += 8) {
        int e0 = g_srcidx[i];
        int e1 = g_srcidx[i + 2];
        int e2 = g_srcidx[i + 4];
        int e3 = g_srcidx[i + 6];
        uint4 v0 = hs[(size_t)e0 * 16 + c];
        uint4 v1 = hs[(size_t)e1 * 16 + c];
        uint4 v2 = hs[(size_t)e2 * 16 + c];
        uint4 v3 = hs[(size_t)e3 * 16 + c];
        acc8(a, v0); acc8(a, v1); acc8(a, v2); acc8(a, v3);
    }
    for (; i < s1; i += 2) acc8(a, hs[(size_t)g_srcidx[i] * 16 + c]);

#pragma unroll
    for (int q = 0; q < 8; q++) a[q] += __shfl_down_sync(0xffffffffu, a[q], 16);

    if (hw == 0) {
        float dv = g_dinv[warp];
        float4 b0 = ((const float4*)bias)[2 * c];
        float4 b1 = ((const float4*)bias)[2 * c + 1];
        __half2 h0 = __floats2half2_rn(fmaxf(fmaf(dv, a[0], b0.x), 0.f),
                                       fmaxf(fmaf(dv, a[1], b0.y), 0.f));
        __half2 h1 = __floats2half2_rn(fmaxf(fmaf(dv, a[2], b0.z), 0.f),
                                       fmaxf(fmaf(dv, a[3], b0.w), 0.f));
        __half2 h2 = __floats2half2_rn(fmaxf(fmaf(dv, a[4], b1.x), 0.f),
                                       fmaxf(fmaf(dv, a[5], b1.y), 0.f));
        __half2 h3 = __floats2half2_rn(fmaxf(fmaf(dv, a[6], b1.z), 0.f),
                                       fmaxf(fmaf(dv, a[7], b1.w), 0.f));
        uint4 o;
        o.x = *(unsigned*)&h0; o.y = *(unsigned*)&h1;
        o.z = *(unsigned*)&h2; o.w = *(unsigned*)&h3;
        out[(size_t)warp * 16 + c] = o;
    }
}

// ---------------- fused pool + MLP head (fp32 math, exact) ------------------
__global__ void __launch_bounds__(128) k_head(
        const __half* __restrict__ h, const int* __restrict__ batch,
        const float* __restrict__ W3, const float* __restrict__ b3,
        const float* __restrict__ W4, const float* __restrict__ b4,
        float* __restrict__ out) {
    __shared__ float sp[128];
    __shared__ float sm2[128];
    int g = blockIdx.x;
    int c = threadIdx.x;

    int lo = 0, hi = N_NODES;
    while (lo < hi) { int mid = (lo + hi) >> 1; if (batch[mid] < g) lo = mid + 1; else hi = mid; }
    int start = lo;
    lo = start; hi = N_NODES;
    while (lo < hi) { int mid = (lo + hi) >> 1; if (batch[mid] < g + 1) lo = mid + 1; else hi = mid; }
    int end = lo;

    float acc = 0.f;
    for (int r = start; r < end; r++) acc += __half2float(h[(size_t)r * HID + c]);
    int cnt = end - start;
    sp[c] = acc / (float)(cnt > 0 ? cnt : 1);
    __syncthreads();

    float m = 0.f;
#pragma unroll 8
    for (int k = 0; k < HID; k++) m = fmaf(sp[k], W3[k * HID + c], m);
    sm2[c] = fmaxf(m + b3[c], 0.f);
    __syncthreads();

    if (c < OUT_CH) {
        float o = 0.f;
#pragma unroll 8
        for (int k = 0; k < HID; k++) o = fmaf(sm2[k], W4[k * OUT_CH + c], o);
        out[g * OUT_CH + c] = o + b4[c];
    }
}

// ---------------- launch ------------------------------------------------------
extern "C" void kernel_launch(void* const* d_in, const int* in_sizes, int n_in,
                              void* d_out, int out_size) {
    const float* x   = (const float*)d_in[0];
    const int*   ei  = (const int*)d_in[1];
    const int*   bat = (const int*)d_in[2];
    const float* W1  = (const float*)d_in[3];
    const float* b1  = (const float*)d_in[4];
    const float* W2  = (const float*)d_in[5];
    const float* b2  = (const float*)d_in[6];
    const float* W3  = (const float*)d_in[7];
    const float* b3  = (const float*)d_in[8];
    const float* W4  = (const float*)d_in[9];
    const float* b4  = (const float*)d_in[10];
    float* out = (float*)d_out;

    __half* hs; __half* h2; float* dinv; int* deg;
    cudaGetSymbolAddress((void**)&hs,   g_hs);
    cudaGetSymbolAddress((void**)&h2,   g_h2);
    cudaGetSymbolAddress((void**)&dinv, g_dinv);
    cudaGetSymbolAddress((void**)&deg,  g_deg);

    const int SMG = 2 * 128 * 136 * 2;   // 69632 B (A + B fp16)
    cudaFuncSetAttribute(k_gemm_mma<false>, cudaFuncAttributeMaxDynamicSharedMemorySize, SMG);
    cudaFuncSetAttribute(k_gemm_mma<true>,  cudaFuncAttributeMaxDynamicSharedMemorySize, SMG);

    const int TB = 256;
    int nbE = (N_EDGES + TB - 1) / TB;
    int nbAgg = (N_NODES * 32 + TB - 1) / TB;
    int nbGemmN = (N_NODES + 127) / 128;    // 782

    // CSR build
    cudaMemsetAsync(deg, 0, N_NODES * sizeof(int));
    k_count<<<nbE, TB>>>(ei);
    k_scan1<<<NB_SCAN, 1024>>>();
    k_scan3<<<NB_SCAN, 1024>>>(NB_SCAN);
    k_scatter<<<nbE, TB>>>(ei);

    // conv1: hs = fp16(dinv * (x @ W1)); h2 = fp16(relu(dinv * gather(hs) + b1))
    k_gemm_mma<false><<<nbGemmN, 256, SMG>>>(x, W1, dinv, hs, N_NODES);
    k_agg<<<nbAgg, TB>>>((const uint4*)hs, b1, (uint4*)h2);

    // conv2 (fp16 input path)
    k_gemm_mma<true><<<nbGemmN, 256, SMG>>>(h2, W2, dinv, hs, N_NODES);
    k_agg<<<nbAgg, TB>>>((const uint4*)hs, b2, (uint4*)h2);

    // fused pool + MLP head (exact fp32)
    k_head<<<N_GRAPHS, 128>>>(h2, bat, W3, b3, W4, b4, out);
}

// round 8
// speedup vs baseline: 1.5743x; 1.0551x over previous
#include <cuda_runtime.h>
#include <cuda_fp16.h>
#include <cstdint>

#define N_NODES  100000
#define N_EDGES  1600000
#define IN_CH    128
#define HID      128
#define OUT_CH   64
#define N_GRAPHS 512

static const int NB_SCAN = (N_NODES + 1023) / 1024;   // 98

// ---------------- scratch (device globals) ----------------------------------
__device__ int    g_deg[N_NODES];
__device__ int    g_incl[N_NODES];
__device__ int    g_bsum[128];
__device__ int    g_rowptr[N_NODES + 1];
__device__ int    g_cursor[N_NODES];
__device__ int    g_srcidx[N_EDGES];
__device__ float  g_dinv[N_NODES];
__device__ __half g_hs[(size_t)N_NODES * HID];     // fp16 GEMM output (gather src)
__device__ __half g_h2[(size_t)N_NODES * HID];     // fp16 conv output
__device__ __half g_Wt[HID * HID];                 // fp16 W^T (n,k) staging

// ---------------- CSR build --------------------------------------------------
// 4 edges per thread (int4 load), independent fire-and-forget atomics.
__global__ void k_count(const int* __restrict__ ei) {
    int t = blockIdx.x * blockDim.x + threadIdx.x;
    if (t * 4 >= N_EDGES) return;
    int4 d = ((const int4*)(ei + N_EDGES))[t];
    atomicAdd(&g_deg[d.x], 1);
    atomicAdd(&g_deg[d.y], 1);
    atomicAdd(&g_deg[d.z], 1);
    atomicAdd(&g_deg[d.w], 1);
}

__global__ void k_scan1() {
    __shared__ int s[1024];
    int t = threadIdx.x;
    int i = blockIdx.x * 1024 + t;
    int v = (i < N_NODES) ? g_deg[i] : 0;
    s[t] = v;
    __syncthreads();
    for (int off = 1; off < 1024; off <<= 1) {
        int a = (t >= off) ? s[t - off] : 0;
        __syncthreads();
        s[t] += a;
        __syncthreads();
    }
    if (i < N_NODES) g_incl[i] = s[t];
    if (t == 1023) g_bsum[blockIdx.x] = s[1023];
}

// scan3 computes its own block offset from g_bsum (no separate scan2 kernel)
__global__ void k_scan3(int nb) {
    __shared__ int tmp[128];
    __shared__ int soff;
    int t = threadIdx.x;
    if (t < 128) tmp[t] = (t < (int)blockIdx.x && t < nb) ? g_bsum[t] : 0;
    __syncthreads();
    if (t == 0) {
        int s = 0;
#pragma unroll
        for (int j = 0; j < 128; j++) s += tmp[j];
        soff = s;
    }
    __syncthreads();
    int i = blockIdx.x * 1024 + t;
    if (i < N_NODES) {
        int d = g_deg[i];
        int v = g_incl[i] - d + soff;      // exclusive prefix
        g_rowptr[i] = v;
        g_cursor[i] = v;
        g_dinv[i]   = rsqrtf((float)(d + 1));
    }
    if (i == 0) g_rowptr[N_NODES] = N_EDGES;
}

// 4 edges per thread: 4 independent atomic->store chains overlap L2 latency.
__global__ void k_scatter(const int* __restrict__ ei) {
    int t = blockIdx.x * blockDim.x + threadIdx.x;
    if (t * 4 >= N_EDGES) return;
    int4 s = ((const int4*)ei)[t];
    int4 d = ((const int4*)(ei + N_EDGES))[t];
    int p0 = atomicAdd(&g_cursor[d.x], 1);
    int p1 = atomicAdd(&g_cursor[d.y], 1);
    int p2 = atomicAdd(&g_cursor[d.z], 1);
    int p3 = atomicAdd(&g_cursor[d.w], 1);
    g_srcidx[p0] = s.x;
    g_srcidx[p1] = s.y;
    g_srcidx[p2] = s.z;
    g_srcidx[p3] = s.w;
}

// ---------------- W transpose to fp16 (once per conv) -----------------------
// Wt[n][k] = fp16(W[k][n]); 32x32 smem tiles, coalesced both sides.
__global__ void k_wt(const float* __restrict__ W) {
    __shared__ float tile[32][33];
    int bx = blockIdx.x, by = blockIdx.y;      // tile col(n) / row(k) base /32
    int tx = threadIdx.x, ty = threadIdx.y;
    int k = by * 32 + ty, n = bx * 32 + tx;
    tile[ty][tx] = W[k * HID + n];
    __syncthreads();
    int on = bx * 32 + ty, ok = by * 32 + tx;
    g_Wt[on * HID + ok] = __float2half_rn(tile[tx][ty]);
}

// ---------------- tensor-core GEMM (128x128 W, K=128) -----------------------
// out[row] = fp16( scale[row] * (X[row] @ W) ), mma m16n8k16 fp16->fp32.
// B read from pre-transposed fp16 g_Wt (pure uint4 copies into smem).
template <bool HALF_IN>
__global__ void __launch_bounds__(256) k_gemm_mma(
        const void* __restrict__ Xv,
        const float* __restrict__ scale, __half* __restrict__ out, int M) {
    constexpr int NT = 16;                        // 128 cols / 8
    constexpr int AS = 136;                       // padded stride (halves)
    extern __shared__ __half sm[];
    __half* Asm = sm;                             // [128][AS]
    __half* Bt  = sm + 128 * AS;                  // [128][AS] (n,k)
    int t = threadIdx.x;
    int rowBase = blockIdx.x * 128;

    if (HALF_IN) {
        const uint4* X = (const uint4*)Xv;        // 16 uint4 per row
        for (int idx = t; idx < 128 * 16; idx += 256) {
            int r = idx >> 4, c8 = idx & 15;
            uint4 v = make_uint4(0u, 0u, 0u, 0u);
            int gr = rowBase + r;
            if (gr < M) v = X[(size_t)gr * 16 + c8];
            *(uint4*)&Asm[r * AS + c8 * 8] = v;
        }
    } else {
        const float4* X = (const float4*)Xv;
        for (int idx = t; idx < 128 * 32; idx += 256) {
            int r = idx >> 5, c4 = idx & 31;
            float4 v = make_float4(0.f, 0.f, 0.f, 0.f);
            int gr = rowBase + r;
            if (gr < M) v = X[(size_t)gr * 32 + c4];
            *(__half2*)&Asm[r * AS + c4 * 4]     = __floats2half2_rn(v.x, v.y);
            *(__half2*)&Asm[r * AS + c4 * 4 + 2] = __floats2half2_rn(v.z, v.w);
        }
    }
    // stage pre-transposed fp16 W: straight uint4 copies, conflict-free
    {
        const uint4* Wt4 = (const uint4*)g_Wt;
        for (int idx = t; idx < 128 * 16; idx += 256) {
            int n = idx >> 4, c8 = idx & 15;
            *(uint4*)&Bt[n * AS + c8 * 8] = Wt4[idx];
        }
    }
    __syncthreads();

    int w = t >> 5, lane = t & 31;
    int g = lane >> 2, s = lane & 3;
    int strip = w * 16;

    float acc[NT][4];
#pragma unroll
    for (int nt = 0; nt < NT; nt++)
#pragma unroll
        for (int q = 0; q < 4; q++) acc[nt][q] = 0.f;

    const __half* Arow0 = &Asm[(strip + g) * AS + s * 2];
    const __half* Arow1 = Arow0 + 8 * AS;
#pragma unroll
    for (int ks = 0; ks < 8; ks++) {
        int kb = ks * 16;
        unsigned a0 = *(const unsigned*)(Arow0 + kb);
        unsigned a1 = *(const unsigned*)(Arow1 + kb);
        unsigned a2 = *(const unsigned*)(Arow0 + kb + 8);
        unsigned a3 = *(const unsigned*)(Arow1 + kb + 8);
#pragma unroll
        for (int nt = 0; nt < NT; nt++) {
            const __half* Bp = &Bt[(nt * 8 + g) * AS + kb + s * 2];
            unsigned b0 = *(const unsigned*)(Bp);
            unsigned b1 = *(const unsigned*)(Bp + 8);
            asm volatile(
                "mma.sync.aligned.m16n8k16.row.col.f32.f16.f16.f32 "
                "{%0,%1,%2,%3}, {%4,%5,%6,%7}, {%8,%9}, {%0,%1,%2,%3};"
                : "+f"(acc[nt][0]), "+f"(acc[nt][1]), "+f"(acc[nt][2]), "+f"(acc[nt][3])
                : "r"(a0), "r"(a1), "r"(a2), "r"(a3), "r"(b0), "r"(b1));
        }
    }

    int gr0 = rowBase + strip + g;
    int gr1 = gr0 + 8;
    float dv0 = (gr0 < M) ? scale[gr0] : 0.f;
    float dv1 = (gr1 < M) ? scale[gr1] : 0.f;
#pragma unroll
    for (int nt = 0; nt < NT; nt++) {
        int col = nt * 8 + s * 2;
        if (gr0 < M)
            *(__half2*)&out[(size_t)gr0 * HID + col] =
                __floats2half2_rn(acc[nt][0] * dv0, acc[nt][1] * dv0);
        if (gr1 < M)
            *(__half2*)&out[(size_t)gr1 * HID + col] =
                __floats2half2_rn(acc[nt][2] * dv1, acc[nt][3] * dv1);
    }
}

// ---------------- aggregation: warp per node, 2 half-warps, LDG.128 ---------
__device__ __forceinline__ void acc8(float* a, uint4 u) {
    const __half2* h = (const __half2*)&u;
#pragma unroll
    for (int j = 0; j < 4; j++) {
        float2 f = __half22float2(h[j]);
        a[2 * j]     += f.x;
        a[2 * j + 1] += f.y;
    }
}

__global__ void __launch_bounds__(256) k_agg(
        const uint4* __restrict__ hs, const float* __restrict__ bias,
        uint4* __restrict__ out) {
    int warp = (blockIdx.x * blockDim.x + threadIdx.x) >> 5;
    int lane = threadIdx.x & 31;
    if (warp >= N_NODES) return;
    int hw = lane >> 4, c = lane & 15;

    float a[8] = {0.f, 0.f, 0.f, 0.f, 0.f, 0.f, 0.f, 0.f};
    if (hw == 0) acc8(a, hs[(size_t)warp * 16 + c]);   // self loop

    int s0 = g_rowptr[warp];
    int s1 = g_rowptr[warp + 1];
    int i = s0 + hw;
    for (; i + 14 < s1; i += 16) {         // 8 edges per half-warp in flight
        int e[8];
#pragma unroll
        for (int q = 0; q < 8; q++) e[q] = g_srcidx[i + 2 * q];
        uint4 v[8];
#pragma unroll
        for (int q = 0; q < 8; q++) v[q] = hs[(size_t)e[q] * 16 + c];
#pragma unroll
        for (int q = 0; q < 8; q++) acc8(a, v[q]);
    }
    for (; i + 6 < s1; i += 8) {
        int e0 = g_srcidx[i];
        int e1 = g_srcidx[i + 2];
        int e2 = g_srcidx[i + 4];
        int e3 = g_srcidx[i + 6];
        uint4 v0 = hs[(size_t)e0 * 16 + c];
        uint4 v1 = hs[(size_t)e1 * 16 + c];
        uint4 v2 = hs[(size_t)e2 * 16 + c];
        uint4 v3 = hs[(size_t)e3 * 16 + c];
        acc8(a, v0); acc8(a, v1); acc8(a, v2); acc8(a, v3);
    }
    for (; i < s1; i += 2) acc8(a, hs[(size_t)g_srcidx[i] * 16 + c]);

#pragma unroll
    for (int q = 0; q < 8; q++) a[q] += __shfl_down_sync(0xffffffffu, a[q], 16);

    if (hw == 0) {
        float dv = g_dinv[warp];
        float4 b0 = ((const float4*)bias)[2 * c];
        float4 b1 = ((const float4*)bias)[2 * c + 1];
        __half2 h0 = __floats2half2_rn(fmaxf(fmaf(dv, a[0], b0.x), 0.f),
                                       fmaxf(fmaf(dv, a[1], b0.y), 0.f));
        __half2 h1 = __floats2half2_rn(fmaxf(fmaf(dv, a[2], b0.z), 0.f),
                                       fmaxf(fmaf(dv, a[3], b0.w), 0.f));
        __half2 h2 = __floats2half2_rn(fmaxf(fmaf(dv, a[4], b1.x), 0.f),
                                       fmaxf(fmaf(dv, a[5], b1.y), 0.f));
        __half2 h3 = __floats2half2_rn(fmaxf(fmaf(dv, a[6], b1.z), 0.f),
                                       fmaxf(fmaf(dv, a[7], b1.w), 0.f));
        uint4 o;
        o.x = *(unsigned*)&h0; o.y = *(unsigned*)&h1;
        o.z = *(unsigned*)&h2; o.w = *(unsigned*)&h3;
        out[(size_t)warp * 16 + c] = o;
    }
}

// ---------------- fused pool + MLP head (fp32 math, exact) ------------------
__global__ void __launch_bounds__(128) k_head(
        const __half* __restrict__ h, const int* __restrict__ batch,
        const float* __restrict__ W3, const float* __restrict__ b3,
        const float* __restrict__ W4, const float* __restrict__ b4,
        float* __restrict__ out) {
    __shared__ float sp[128];
    __shared__ float sm2[128];
    int g = blockIdx.x;
    int c = threadIdx.x;

    int lo = 0, hi = N_NODES;
    while (lo < hi) { int mid = (lo + hi) >> 1; if (batch[mid] < g) lo = mid + 1; else hi = mid; }
    int start = lo;
    lo = start; hi = N_NODES;
    while (lo < hi) { int mid = (lo + hi) >> 1; if (batch[mid] < g + 1) lo = mid + 1; else hi = mid; }
    int end = lo;

    float acc = 0.f;
    for (int r = start; r < end; r++) acc += __half2float(h[(size_t)r * HID + c]);
    int cnt = end - start;
    sp[c] = acc / (float)(cnt > 0 ? cnt : 1);
    __syncthreads();

    float m = 0.f;
#pragma unroll 8
    for (int k = 0; k < HID; k++) m = fmaf(sp[k], W3[k * HID + c], m);
    sm2[c] = fmaxf(m + b3[c], 0.f);
    __syncthreads();

    if (c < OUT_CH) {
        float o = 0.f;
#pragma unroll 8
        for (int k = 0; k < HID; k++) o = fmaf(sm2[k], W4[k * OUT_CH + c], o);
        out[g * OUT_CH + c] = o + b4[c];
    }
}

// ---------------- launch ------------------------------------------------------
extern "C" void kernel_launch(void* const* d_in, const int* in_sizes, int n_in,
                              void* d_out, int out_size) {
    const float* x   = (const float*)d_in[0];
    const int*   ei  = (const int*)d_in[1];
    const int*   bat = (const int*)d_in[2];
    const float* W1  = (const float*)d_in[3];
    const float* b1  = (const float*)d_in[4];
    const float* W2  = (const float*)d_in[5];
    const float* b2  = (const float*)d_in[6];
    const float* W3  = (const float*)d_in[7];
    const float* b3  = (const float*)d_in[8];
    const float* W4  = (const float*)d_in[9];
    const float* b4  = (const float*)d_in[10];
    float* out = (float*)d_out;

    __half* hs; __half* h2; float* dinv; int* deg;
    cudaGetSymbolAddress((void**)&hs,   g_hs);
    cudaGetSymbolAddress((void**)&h2,   g_h2);
    cudaGetSymbolAddress((void**)&dinv, g_dinv);
    cudaGetSymbolAddress((void**)&deg,  g_deg);

    const int SMG = 2 * 128 * 136 * 2;   // 69632 B (A + B fp16)
    cudaFuncSetAttribute(k_gemm_mma<false>, cudaFuncAttributeMaxDynamicSharedMemorySize, SMG);
    cudaFuncSetAttribute(k_gemm_mma<true>,  cudaFuncAttributeMaxDynamicSharedMemorySize, SMG);

    const int TB = 256;
    int nbE4 = (N_EDGES / 4 + TB - 1) / TB;
    int nbAgg = (N_NODES * 32 + TB - 1) / TB;
    int nbGemmN = (N_NODES + 127) / 128;    // 782

    // CSR build
    cudaMemsetAsync(deg, 0, N_NODES * sizeof(int));
    k_count<<<nbE4, TB>>>(ei);
    k_scan1<<<NB_SCAN, 1024>>>();
    k_scan3<<<NB_SCAN, 1024>>>(NB_SCAN);
    k_scatter<<<nbE4, TB>>>(ei);

    // conv1
    k_wt<<<dim3(4, 4), dim3(32, 32)>>>(W1);
    k_gemm_mma<false><<<nbGemmN, 256, SMG>>>(x, dinv, hs, N_NODES);
    k_agg<<<nbAgg, TB>>>((const uint4*)hs, b1, (uint4*)h2);

    // conv2 (fp16 input path)
    k_wt<<<dim3(4, 4), dim3(32, 32)>>>(W2);
    k_gemm_mma<true><<<nbGemmN, 256, SMG>>>(h2, dinv, hs, N_NODES);
    k_agg<<<nbAgg, TB>>>((const uint4*)hs, b2, (uint4*)h2);

    // fused pool + MLP head (exact fp32)
    k_head<<<N_GRAPHS, 128>>>(h2, bat, W3, b3, W4, b4, out);
}

// round 9
// speedup vs baseline: 1.6314x; 1.0363x over previous
#include <cuda_runtime.h>
#include <cuda_fp16.h>
#include <cstdint>

#define N_NODES  100000
#define N_EDGES  1600000
#define IN_CH    128
#define HID      128
#define OUT_CH   64
#define N_GRAPHS 512

static const int NB_SCAN = (N_NODES + 1023) / 1024;   // 98

// ---------------- scratch (device globals) ----------------------------------
__device__ int    g_deg[N_NODES];
__device__ int    g_incl[N_NODES];
__device__ int    g_bsum[128];
__device__ int    g_rowptr[N_NODES + 1];
__device__ int    g_rank[N_EDGES];                 // per-edge rank within dest
__device__ int    g_srcidx[N_EDGES];
__device__ float  g_dinv[N_NODES];
__device__ __half g_hs[(size_t)N_NODES * HID];     // fp16 GEMM output (gather src)
__device__ __half g_h2[(size_t)N_NODES * HID];     // fp16 conv output
__device__ __half g_Wt1[HID * HID];                // fp16 W1^T (n,k)
__device__ __half g_Wt2[HID * HID];                // fp16 W2^T (n,k)

// ---------------- side stream / events (static init: in memory baseline) ----
struct ForkRes {
    cudaStream_t s2;
    cudaEvent_t  evA, evB;
    ForkRes() {
        cudaStreamCreateWithFlags(&s2, cudaStreamNonBlocking);
        cudaEventCreateWithFlags(&evA, cudaEventDisableTiming);
        cudaEventCreateWithFlags(&evB, cudaEventDisableTiming);
    }
};
static ForkRes g_fork;

// ---------------- CSR build --------------------------------------------------
// count + rank capture: 4 edges/thread; rank store is coalesced.
__global__ void k_count(const int* __restrict__ ei) {
    int t = blockIdx.x * blockDim.x + threadIdx.x;
    if (t * 4 >= N_EDGES) return;
    int4 d = ((const int4*)(ei + N_EDGES))[t];
    int4 r;
    r.x = atomicAdd(&g_deg[d.x], 1);
    r.y = atomicAdd(&g_deg[d.y], 1);
    r.z = atomicAdd(&g_deg[d.z], 1);
    r.w = atomicAdd(&g_deg[d.w], 1);
    ((int4*)g_rank)[t] = r;
}

__global__ void k_dinv() {
    int i = blockIdx.x * blockDim.x + threadIdx.x;
    if (i < N_NODES) g_dinv[i] = rsqrtf((float)(g_deg[i] + 1));
}

__global__ void k_scan1() {
    __shared__ int s[1024];
    int t = threadIdx.x;
    int i = blockIdx.x * 1024 + t;
    int v = (i < N_NODES) ? g_deg[i] : 0;
    s[t] = v;
    __syncthreads();
    for (int off = 1; off < 1024; off <<= 1) {
        int a = (t >= off) ? s[t - off] : 0;
        __syncthreads();
        s[t] += a;
        __syncthreads();
    }
    if (i < N_NODES) g_incl[i] = s[t];
    if (t == 1023) g_bsum[blockIdx.x] = s[1023];
}

// rowptr only; block offset recomputed from g_bsum (no scan2 kernel)
__global__ void k_scan3(int nb) {
    __shared__ int tmp[128];
    __shared__ int soff;
    int t = threadIdx.x;
    if (t < 128) tmp[t] = (t < (int)blockIdx.x && t < nb) ? g_bsum[t] : 0;
    __syncthreads();
    if (t == 0) {
        int s = 0;
#pragma unroll
        for (int j = 0; j < 128; j++) s += tmp[j];
        soff = s;
    }
    __syncthreads();
    int i = blockIdx.x * 1024 + t;
    if (i < N_NODES)
        g_rowptr[i] = g_incl[i] - g_deg[i] + soff;   // exclusive prefix
    if (i == 0) g_rowptr[N_NODES] = N_EDGES;
}

// atomic-free scatter: pos = rowptr[dst] + rank (precomputed in k_count)
__global__ void k_scatter(const int* __restrict__ ei) {
    int t = blockIdx.x * blockDim.x + threadIdx.x;
    if (t * 4 >= N_EDGES) return;
    int4 s = ((const int4*)ei)[t];
    int4 d = ((const int4*)(ei + N_EDGES))[t];
    int4 r = ((const int4*)g_rank)[t];
    g_srcidx[g_rowptr[d.x] + r.x] = s.x;
    g_srcidx[g_rowptr[d.y] + r.y] = s.y;
    g_srcidx[g_rowptr[d.z] + r.z] = s.z;
    g_srcidx[g_rowptr[d.w] + r.w] = s.w;
}

// ---------------- W transpose to fp16 ----------------------------------------
__global__ void k_wt(const float* __restrict__ W, __half* __restrict__ Wt) {
    __shared__ float tile[32][33];
    int bx = blockIdx.x, by = blockIdx.y;
    int tx = threadIdx.x, ty = threadIdx.y;
    int k = by * 32 + ty, n = bx * 32 + tx;
    tile[ty][tx] = W[k * HID + n];
    __syncthreads();
    int on = bx * 32 + ty, ok = by * 32 + tx;
    Wt[on * HID + ok] = __float2half_rn(tile[tx][ty]);
}

// ---------------- tensor-core GEMM (128x128 W, K=128) -----------------------
template <bool HALF_IN>
__global__ void __launch_bounds__(256) k_gemm_mma(
        const void* __restrict__ Xv, const __half* __restrict__ Wt,
        const float* __restrict__ scale, __half* __restrict__ out, int M) {
    constexpr int NT = 16;                        // 128 cols / 8
    constexpr int AS = 136;                       // padded stride (halves)
    extern __shared__ __half sm[];
    __half* Asm = sm;                             // [128][AS]
    __half* Bt  = sm + 128 * AS;                  // [128][AS] (n,k)
    int t = threadIdx.x;
    int rowBase = blockIdx.x * 128;

    if (HALF_IN) {
        const uint4* X = (const uint4*)Xv;
        for (int idx = t; idx < 128 * 16; idx += 256) {
            int r = idx >> 4, c8 = idx & 15;
            uint4 v = make_uint4(0u, 0u, 0u, 0u);
            int gr = rowBase + r;
            if (gr < M) v = X[(size_t)gr * 16 + c8];
            *(uint4*)&Asm[r * AS + c8 * 8] = v;
        }
    } else {
        const float4* X = (const float4*)Xv;
        for (int idx = t; idx < 128 * 32; idx += 256) {
            int r = idx >> 5, c4 = idx & 31;
            float4 v = make_float4(0.f, 0.f, 0.f, 0.f);
            int gr = rowBase + r;
            if (gr < M) v = X[(size_t)gr * 32 + c4];
            *(__half2*)&Asm[r * AS + c4 * 4]     = __floats2half2_rn(v.x, v.y);
            *(__half2*)&Asm[r * AS + c4 * 4 + 2] = __floats2half2_rn(v.z, v.w);
        }
    }
    {
        const uint4* Wt4 = (const uint4*)Wt;
        for (int idx = t; idx < 128 * 16; idx += 256) {
            int n = idx >> 4, c8 = idx & 15;
            *(uint4*)&Bt[n * AS + c8 * 8] = Wt4[idx];
        }
    }
    __syncthreads();

    int w = t >> 5, lane = t & 31;
    int g = lane >> 2, s = lane & 3;
    int strip = w * 16;

    float acc[NT][4];
#pragma unroll
    for (int nt = 0; nt < NT; nt++)
#pragma unroll
        for (int q = 0; q < 4; q++) acc[nt][q] = 0.f;

    const __half* Arow0 = &Asm[(strip + g) * AS + s * 2];
    const __half* Arow1 = Arow0 + 8 * AS;
#pragma unroll
    for (int ks = 0; ks < 8; ks++) {
        int kb = ks * 16;
        unsigned a0 = *(const unsigned*)(Arow0 + kb);
        unsigned a1 = *(const unsigned*)(Arow1 + kb);
        unsigned a2 = *(const unsigned*)(Arow0 + kb + 8);
        unsigned a3 = *(const unsigned*)(Arow1 + kb + 8);
#pragma unroll
        for (int nt = 0; nt < NT; nt++) {
            const __half* Bp = &Bt[(nt * 8 + g) * AS + kb + s * 2];
            unsigned b0 = *(const unsigned*)(Bp);
            unsigned b1 = *(const unsigned*)(Bp + 8);
            asm volatile(
                "mma.sync.aligned.m16n8k16.row.col.f32.f16.f16.f32 "
                "{%0,%1,%2,%3}, {%4,%5,%6,%7}, {%8,%9}, {%0,%1,%2,%3};"
                : "+f"(acc[nt][0]), "+f"(acc[nt][1]), "+f"(acc[nt][2]), "+f"(acc[nt][3])
                : "r"(a0), "r"(a1), "r"(a2), "r"(a3), "r"(b0), "r"(b1));
        }
    }

    int gr0 = rowBase + strip + g;
    int gr1 = gr0 + 8;
    float dv0 = (gr0 < M) ? scale[gr0] : 0.f;
    float dv1 = (gr1 < M) ? scale[gr1] : 0.f;
#pragma unroll
    for (int nt = 0; nt < NT; nt++) {
        int col = nt * 8 + s * 2;
        if (gr0 < M)
            *(__half2*)&out[(size_t)gr0 * HID + col] =
                __floats2half2_rn(acc[nt][0] * dv0, acc[nt][1] * dv0);
        if (gr1 < M)
            *(__half2*)&out[(size_t)gr1 * HID + col] =
                __floats2half2_rn(acc[nt][2] * dv1, acc[nt][3] * dv1);
    }
}

// ---------------- aggregation: warp per node, 2 half-warps, LDG.128 ---------
__device__ __forceinline__ void acc8(float* a, uint4 u) {
    const __half2* h = (const __half2*)&u;
#pragma unroll
    for (int j = 0; j < 4; j++) {
        float2 f = __half22float2(h[j]);
        a[2 * j]     += f.x;
        a[2 * j + 1] += f.y;
    }
}

__global__ void __launch_bounds__(256) k_agg(
        const uint4* __restrict__ hs, const float* __restrict__ bias,
        uint4* __restrict__ out) {
    int warp = (blockIdx.x * blockDim.x + threadIdx.x) >> 5;
    int lane = threadIdx.x & 31;
    if (warp >= N_NODES) return;
    int hw = lane >> 4, c = lane & 15;

    float a[8] = {0.f, 0.f, 0.f, 0.f, 0.f, 0.f, 0.f, 0.f};
    if (hw == 0) acc8(a, hs[(size_t)warp * 16 + c]);   // self loop

    int s0 = g_rowptr[warp];
    int s1 = g_rowptr[warp + 1];
    int i = s0 + hw;
    for (; i + 14 < s1; i += 16) {
        int e[8];
#pragma unroll
        for (int q = 0; q < 8; q++) e[q] = g_srcidx[i + 2 * q];
        uint4 v[8];
#pragma unroll
        for (int q = 0; q < 8; q++) v[q] = hs[(size_t)e[q] * 16 + c];
#pragma unroll
        for (int q = 0; q < 8; q++) acc8(a, v[q]);
    }
    for (; i + 6 < s1; i += 8) {
        int e0 = g_srcidx[i];
        int e1 = g_srcidx[i + 2];
        int e2 = g_srcidx[i + 4];
        int e3 = g_srcidx[i + 6];
        uint4 v0 = hs[(size_t)e0 * 16 + c];
        uint4 v1 = hs[(size_t)e1 * 16 + c];
        uint4 v2 = hs[(size_t)e2 * 16 + c];
        uint4 v3 = hs[(size_t)e3 * 16 + c];
        acc8(a, v0); acc8(a, v1); acc8(a, v2); acc8(a, v3);
    }
    for (; i < s1; i += 2) acc8(a, hs[(size_t)g_srcidx[i] * 16 + c]);

#pragma unroll
    for (int q = 0; q < 8; q++) a[q] += __shfl_down_sync(0xffffffffu, a[q], 16);

    if (hw == 0) {
        float dv = g_dinv[warp];
        float4 b0 = ((const float4*)bias)[2 * c];
        float4 b1 = ((const float4*)bias)[2 * c + 1];
        __half2 h0 = __floats2half2_rn(fmaxf(fmaf(dv, a[0], b0.x), 0.f),
                                       fmaxf(fmaf(dv, a[1], b0.y), 0.f));
        __half2 h1 = __floats2half2_rn(fmaxf(fmaf(dv, a[2], b0.z), 0.f),
                                       fmaxf(fmaf(dv, a[3], b0.w), 0.f));
        __half2 h2 = __floats2half2_rn(fmaxf(fmaf(dv, a[4], b1.x), 0.f),
                                       fmaxf(fmaf(dv, a[5], b1.y), 0.f));
        __half2 h3 = __floats2half2_rn(fmaxf(fmaf(dv, a[6], b1.z), 0.f),
                                       fmaxf(fmaf(dv, a[7], b1.w), 0.f));
        uint4 o;
        o.x = *(unsigned*)&h0; o.y = *(unsigned*)&h1;
        o.z = *(unsigned*)&h2; o.w = *(unsigned*)&h3;
        out[(size_t)warp * 16 + c] = o;
    }
}

// ---------------- fused pool + MLP head (fp32 math, exact) ------------------
__global__ void __launch_bounds__(128) k_head(
        const __half* __restrict__ h, const int* __restrict__ batch,
        const float* __restrict__ W3, const float* __restrict__ b3,
        const float* __restrict__ W4, const float* __restrict__ b4,
        float* __restrict__ out) {
    __shared__ float sp[128];
    __shared__ float sm2[128];
    int g = blockIdx.x;
    int c = threadIdx.x;

    int lo = 0, hi = N_NODES;
    while (lo < hi) { int mid = (lo + hi) >> 1; if (batch[mid] < g) lo = mid + 1; else hi = mid; }
    int start = lo;
    lo = start; hi = N_NODES;
    while (lo < hi) { int mid = (lo + hi) >> 1; if (batch[mid] < g + 1) lo = mid + 1; else hi = mid; }
    int end = lo;

    float acc = 0.f;
    for (int r = start; r < end; r++) acc += __half2float(h[(size_t)r * HID + c]);
    int cnt = end - start;
    sp[c] = acc / (float)(cnt > 0 ? cnt : 1);
    __syncthreads();

    float m = 0.f;
#pragma unroll 8
    for (int k = 0; k < HID; k++) m = fmaf(sp[k], W3[k * HID + c], m);
    sm2[c] = fmaxf(m + b3[c], 0.f);
    __syncthreads();

    if (c < OUT_CH) {
        float o = 0.f;
#pragma unroll 8
        for (int k = 0; k < HID; k++) o = fmaf(sm2[k], W4[k * OUT_CH + c], o);
        out[g * OUT_CH + c] = o + b4[c];
    }
}

// ---------------- launch ------------------------------------------------------
extern "C" void kernel_launch(void* const* d_in, const int* in_sizes, int n_in,
                              void* d_out, int out_size) {
    const float* x   = (const float*)d_in[0];
    const int*   ei  = (const int*)d_in[1];
    const int*   bat = (const int*)d_in[2];
    const float* W1  = (const float*)d_in[3];
    const float* b1  = (const float*)d_in[4];
    const float* W2  = (const float*)d_in[5];
    const float* b2  = (const float*)d_in[6];
    const float* W3  = (const float*)d_in[7];
    const float* b3  = (const float*)d_in[8];
    const float* W4  = (const float*)d_in[9];
    const float* b4  = (const float*)d_in[10];
    float* out = (float*)d_out;

    __half* hs; __half* h2; float* dinv; int* deg; __half* wt1; __half* wt2;
    cudaGetSymbolAddress((void**)&hs,   g_hs);
    cudaGetSymbolAddress((void**)&h2,   g_h2);
    cudaGetSymbolAddress((void**)&dinv, g_dinv);
    cudaGetSymbolAddress((void**)&deg,  g_deg);
    cudaGetSymbolAddress((void**)&wt1,  g_Wt1);
    cudaGetSymbolAddress((void**)&wt2,  g_Wt2);

    const int SMG = 2 * 128 * 136 * 2;   // 69632 B
    cudaFuncSetAttribute(k_gemm_mma<false>, cudaFuncAttributeMaxDynamicSharedMemorySize, SMG);
    cudaFuncSetAttribute(k_gemm_mma<true>,  cudaFuncAttributeMaxDynamicSharedMemorySize, SMG);

    const int TB = 256;
    int nbN = (N_NODES + TB - 1) / TB;
    int nbE4 = (N_EDGES / 4 + TB - 1) / TB;
    int nbAgg = (N_NODES * 32 + TB - 1) / TB;
    int nbGemmN = (N_NODES + 127) / 128;    // 782

    cudaStream_t s2 = g_fork.s2;

    // count (writes deg + ranks) on main stream
    cudaMemsetAsync(deg, 0, N_NODES * sizeof(int));
    k_count<<<nbE4, TB>>>(ei);

    // fork: side stream does dinv -> Wt -> GEMM1 while main does scan+scatter
    cudaEventRecord(g_fork.evA, 0);
    cudaStreamWaitEvent(s2, g_fork.evA, 0);

    k_dinv<<<nbN, TB, 0, s2>>>();
    k_wt<<<dim3(4, 4), dim3(32, 32), 0, s2>>>(W1, wt1);
    k_wt<<<dim3(4, 4), dim3(32, 32), 0, s2>>>(W2, wt2);
    k_gemm_mma<false><<<nbGemmN, 256, SMG, s2>>>(x, wt1, dinv, hs, N_NODES);
    cudaEventRecord(g_fork.evB, s2);

    k_scan1<<<NB_SCAN, 1024>>>();
    k_scan3<<<NB_SCAN, 1024>>>(NB_SCAN);
    k_scatter<<<nbE4, TB>>>(ei);

    // join
    cudaStreamWaitEvent(0, g_fork.evB, 0);

    // conv1 aggregation, conv2, head (main stream)
    k_agg<<<nbAgg, TB>>>((const uint4*)hs, b1, (uint4*)h2);
    k_gemm_mma<true><<<nbGemmN, 256, SMG>>>(h2, wt2, dinv, hs, N_NODES);
    k_agg<<<nbAgg, TB>>>((const uint4*)hs, b2, (uint4*)h2);
    k_head<<<N_GRAPHS, 128>>>(h2, bat, W3, b3, W4, b4, out);
}